// round 9
// baseline (speedup 1.0000x reference)
#include <cuda_runtime.h>

// Sizes: x (256,4096) f32, weights (64,64,64) f32, out (256,4096) f32.
// out[b, f*64+n] = sum_c sum_m w[f,c,m] * x[b, c*64 + (n-m) mod 64]
// computed in the 64-point DFT domain with rfft symmetry (33 freqs).

#define NF 33
#define BSZ 256
#define CC 64
#define FF 64

// [k][row] planes. Wf rows = f*64+c (4096), Xf rows = b*64+c (16384),
// S rows = b*64+f (16384).
__device__ float2 g_Wf[NF * FF * CC];
__device__ float2 g_Xf[NF * BSZ * CC];
__device__ float2 g_S [NF * BSZ * FF];

// ---------------------------------------------------------------------------
// Kernel 1: forward rDFT of every length-64 row (4096 w-rows + 16384 x-rows).
// Radix-2: e[j] = v[j]+v[j+32], o[j] = v[j]-v[j+32];
//   X[k] = sum_{j<32} (k even ? e[j] : o[j]) * tw[(j*k)&63],  k = 0..31
//   X[32] = sum_j (-1)^j e[j].
// CTA = 32 rows x 256 thr, grid 640 (~4.3 CTAs/SM, smem ~28KB -> occupancy).
// Coalesced loads; e/o transposed [j][r] pitch 36; compute warp = 4 rows,
// lane = k (broadcast float4 reads); outputs staged and stored coalesced.
// ---------------------------------------------------------------------------
__global__ void __launch_bounds__(256) k_dft(const float* __restrict__ x,
                                             const float* __restrict__ w) {
    __shared__ float  esm[32][36];    // [j][r]
    __shared__ float  osm[32][36];
    __shared__ float  psm[8][36];     // [hq][r] parity partials
    __shared__ float2 Bsm[32][32];    // [j][k]
    __shared__ float2 outsm[33][34];  // [k][r]
    __shared__ float2 tw[64];

    const int t = threadIdx.x;
    const int warp = t >> 5, lane = t & 31;

    if (t < 64) {
        float s, c;
        sincospif(-(float)t * (1.0f / 32.0f), &s, &c);
        tw[t] = make_float2(c, s);
    }
    __syncthreads();
#pragma unroll
    for (int i = t; i < 1024; i += 256) {
        const int j = i >> 5, k = i & 31;
        Bsm[j][k] = tw[(j * k) & 63];
    }

    const int row0 = blockIdx.x * 32;
    const bool isW = row0 < FF * CC;          // first 128 CTAs exactly
    const float* src = isW ? (w + row0 * 64) : (x + (row0 - FF * CC) * 64);
    float2* base = isW ? g_Wf : g_Xf;
    const int plane = isW ? (FF * CC) : (BSZ * CC);
    const int roff = isW ? row0 : (row0 - FF * CC);

    // ---- stage: thread = (row r, quarter hq); coalesced 128B-run loads ----
    {
        const int r = t >> 3;        // 0..31
        const int hq = t & 7;
        const float4* s4 = (const float4*)src;
        const float4 a  = s4[r * 16 + hq];
        const float4 bq = s4[r * 16 + hq + 8];
        const float e0 = a.x + bq.x, e1 = a.y + bq.y;
        const float e2 = a.z + bq.z, e3 = a.w + bq.w;
        esm[4 * hq + 0][r] = e0;  osm[4 * hq + 0][r] = a.x - bq.x;
        esm[4 * hq + 1][r] = e1;  osm[4 * hq + 1][r] = a.y - bq.y;
        esm[4 * hq + 2][r] = e2;  osm[4 * hq + 2][r] = a.z - bq.z;
        esm[4 * hq + 3][r] = e3;  osm[4 * hq + 3][r] = a.w - bq.w;
        psm[hq][r] = e0 - e1 + e2 - e3;       // j = 4hq starts even
    }
    __syncthreads();

    // ---- k = 32 plane into outsm ----
    if (t < 32) {
        float p = 0.0f;
#pragma unroll
        for (int hq = 0; hq < 8; hq++) p += psm[hq][t];
        outsm[32][t] = make_float2(p, 0.0f);
    }

    // ---- compute: warp = 4 rows, lane = frequency k ----
    const int r0 = warp * 4;
    const float* ub = (lane & 1) ? &osm[0][0] : &esm[0][0];

    float ar[4] = {}, ai[4] = {};
#pragma unroll 8
    for (int j = 0; j < 32; j++) {
        const float2 b = Bsm[j][lane];
        const float4 v = *(const float4*)(ub + j * 36 + r0);
        ar[0] = fmaf(v.x, b.x, ar[0]);  ai[0] = fmaf(v.x, b.y, ai[0]);
        ar[1] = fmaf(v.y, b.x, ar[1]);  ai[1] = fmaf(v.y, b.y, ai[1]);
        ar[2] = fmaf(v.z, b.x, ar[2]);  ai[2] = fmaf(v.z, b.y, ai[2]);
        ar[3] = fmaf(v.w, b.x, ar[3]);  ai[3] = fmaf(v.w, b.y, ai[3]);
    }

    // stage results: lane k, rows r0..r0+3  (2 x STS.128, aligned)
    {
        float4* o4 = (float4*)&outsm[lane][r0];
        o4[0] = make_float4(ar[0], ai[0], ar[1], ai[1]);
        o4[1] = make_float4(ar[2], ai[2], ar[3], ai[3]);
    }
    __syncthreads();

    // ---- coalesced stores: 256B runs within each k plane ----
#pragma unroll
    for (int i = t; i < 33 * 32; i += 256) {
        const int k = i >> 5, rl = i & 31;
        base[k * plane + roff + rl] = outsm[k][rl];
    }
}

// ---------------------------------------------------------------------------
// Kernel 2: per-frequency complex GEMM, Karatsuba 3-mult, c-vectorized.
// Grid (4 btiles x 2 ftiles, 33 freqs) = 264 CTAs, 256 thr, smem ~77KB ->
// 2 CTAs/SM resident. Tile 64b x 32f over 64 c; thread = 4b x 2f.
//   Re = a1 - a2,  Im = a3 - a1 - a2
// ---------------------------------------------------------------------------
__global__ void __launch_bounds__(256) k_gemm() {
    extern __shared__ float smf[];
    float2* Xs   = (float2*)smf;                              // [64][66]
    float*  Xsum = smf + 2 * 64 * 66;                         // [64][68]
    float2* Ws   = (float2*)(smf + 2 * 64 * 66 + 64 * 68);    // [32][66]
    float*  Wsum = smf + 2 * 64 * 66 + 64 * 68 + 2 * 32 * 66; // [32][68]

    const int k  = blockIdx.y;
    const int b0 = (blockIdx.x & 3) * 64;
    const int f0 = (blockIdx.x >> 2) * 32;
    const float2* gX = g_Xf + k * (BSZ * CC) + b0 * CC;
    const float2* gW = g_Wf + k * (FF * CC) + f0 * CC;

#pragma unroll
    for (int i = threadIdx.x; i < 4096; i += 256) {
        const int r = i >> 6, c = i & 63;
        const float2 xv = gX[i];
        Xs[r * 66 + c] = xv;
        Xsum[r * 68 + c] = xv.x + xv.y;
    }
#pragma unroll
    for (int i = threadIdx.x; i < 2048; i += 256) {
        const int r = i >> 6, c = i & 63;
        const float2 wv = gW[i];
        Ws[r * 66 + c] = wv;
        Wsum[r * 68 + c] = wv.x + wv.y;
    }
    __syncthreads();

    const int tf = threadIdx.x & 15;   // f = f0 + tf + 16*i (i<2)
    const int tb = threadIdx.x >> 4;   // b = b0 + tb + 16*j (j<4)

    float a1[4][2] = {}, a2[4][2] = {}, a3[4][2] = {};
#pragma unroll 4
    for (int c = 0; c < 64; c += 2) {
        float4 xv[4], wv[2];
        float2 xs[4], ws[2];
#pragma unroll
        for (int j = 0; j < 4; j++) {
            const int b = tb + 16 * j;
            xv[j] = *(const float4*)&Xs[b * 66 + c];      // 2 c-values
            xs[j] = *(const float2*)&Xsum[b * 68 + c];
        }
#pragma unroll
        for (int i = 0; i < 2; i++) {
            const int f = tf + 16 * i;
            wv[i] = *(const float4*)&Ws[f * 66 + c];
            ws[i] = *(const float2*)&Wsum[f * 68 + c];
        }
#pragma unroll
        for (int j = 0; j < 4; j++)
#pragma unroll
            for (int i = 0; i < 2; i++) {
                a1[j][i] = fmaf(xv[j].x, wv[i].x, a1[j][i]);
                a2[j][i] = fmaf(xv[j].y, wv[i].y, a2[j][i]);
                a3[j][i] = fmaf(xs[j].x, ws[i].x, a3[j][i]);
                a1[j][i] = fmaf(xv[j].z, wv[i].z, a1[j][i]);
                a2[j][i] = fmaf(xv[j].w, wv[i].w, a2[j][i]);
                a3[j][i] = fmaf(xs[j].y, ws[i].y, a3[j][i]);
            }
    }

    float2* gS = g_S + k * (BSZ * FF) + b0 * FF + f0;
#pragma unroll
    for (int j = 0; j < 4; j++)
#pragma unroll
        for (int i = 0; i < 2; i++) {
            const float re = a1[j][i] - a2[j][i];
            const float im = a3[j][i] - a1[j][i] - a2[j][i];
            gS[(tb + 16 * j) * FF + tf + 16 * i] = make_float2(re, im);
        }
}

// ---------------------------------------------------------------------------
// Kernel 3: real inverse transform with n / n+32 symmetry:
//   out[r][n]    = E[r][n] + O[r][n]
//   out[r][n+32] = E[r][n] - O[r][n]      (n < 32)
//   E over even k, O over odd k, Bm[k][n] = (s_k cos, -s_k sin),
//   s_k = 1/64 for k in {0,32} else 2/64.
// CTA = 32 rows x 256 thr -> 512 CTAs (~3.5/SM). Thread = (row, 4-wide n).
// ---------------------------------------------------------------------------
__global__ void __launch_bounds__(256) k_inv(float* __restrict__ out) {
    __shared__ float2 Ssh[32][NF];   // [row][k]
    __shared__ float2 Bm[NF][32];    // n < 32 only
    __shared__ float2 tw[64];

    const int t = threadIdx.x;
    if (t < 64) {
        float s, c;
        sincospif((float)t * (1.0f / 32.0f), &s, &c);
        tw[t] = make_float2(c, s);
    }
    __syncthreads();
#pragma unroll
    for (int i = t; i < NF * 32; i += 256) {
        const int k = i >> 5, n = i & 31;
        const float sc = (k == 0 || k == 32) ? (1.0f / 64.0f) : (2.0f / 64.0f);
        const float2 wv = tw[(k * n) & 63];
        Bm[k][n] = make_float2(sc * wv.x, -sc * wv.y);
    }

    const int r0 = blockIdx.x * 32;
#pragma unroll
    for (int i = t; i < 32 * NF; i += 256) {
        const int rl = i & 31, k = i >> 5;
        Ssh[rl][k] = g_S[k * (BSZ * FF) + r0 + rl];
    }
    __syncthreads();

    const int ng  = t & 7;    // n = ng*4 .. ng*4+3 (lower half)
    const int row = t >> 3;   // 0..31

    float e[4] = {}, o[4] = {};
#pragma unroll
    for (int kk = 0; kk < 17; kk++) {          // even k = 0,2,...,32
        const int k = 2 * kk;
        const float2 sv = Ssh[row][k];
        const float4 b01 = *(const float4*)&Bm[k][ng * 4];
        const float4 b23 = *(const float4*)&Bm[k][ng * 4 + 2];
        e[0] = fmaf(sv.x, b01.x, e[0]);  e[0] = fmaf(sv.y, b01.y, e[0]);
        e[1] = fmaf(sv.x, b01.z, e[1]);  e[1] = fmaf(sv.y, b01.w, e[1]);
        e[2] = fmaf(sv.x, b23.x, e[2]);  e[2] = fmaf(sv.y, b23.y, e[2]);
        e[3] = fmaf(sv.x, b23.z, e[3]);  e[3] = fmaf(sv.y, b23.w, e[3]);
    }
#pragma unroll
    for (int kk = 0; kk < 16; kk++) {          // odd k = 1,3,...,31
        const int k = 2 * kk + 1;
        const float2 sv = Ssh[row][k];
        const float4 b01 = *(const float4*)&Bm[k][ng * 4];
        const float4 b23 = *(const float4*)&Bm[k][ng * 4 + 2];
        o[0] = fmaf(sv.x, b01.x, o[0]);  o[0] = fmaf(sv.y, b01.y, o[0]);
        o[1] = fmaf(sv.x, b01.z, o[1]);  o[1] = fmaf(sv.y, b01.w, o[1]);
        o[2] = fmaf(sv.x, b23.x, o[2]);  o[2] = fmaf(sv.y, b23.y, o[2]);
        o[3] = fmaf(sv.x, b23.z, o[3]);  o[3] = fmaf(sv.y, b23.w, o[3]);
    }

    float* obase = out + (r0 + row) * 64 + ng * 4;
    *(float4*)obase = make_float4(e[0] + o[0], e[1] + o[1],
                                  e[2] + o[2], e[3] + o[3]);
    *(float4*)(obase + 32) = make_float4(e[0] - o[0], e[1] - o[1],
                                         e[2] - o[2], e[3] - o[3]);
}

// ---------------------------------------------------------------------------
extern "C" void kernel_launch(void* const* d_in, const int* in_sizes, int n_in,
                              void* d_out, int out_size) {
    const float* x = (const float*)d_in[0];
    const float* w = (const float*)d_in[1];
    // Defensive: identify by element count (x = 1048576, w = 262144).
    if (n_in >= 2 && in_sizes[0] == 64 * 64 * 64) {
        x = (const float*)d_in[1];
        w = (const float*)d_in[0];
    }

    // Xs 33.8K + Xsum 17.4K + Ws 16.9K + Wsum 8.7K = 76800 bytes
    static const size_t gemm_smem =
        (2 * 64 * 66 + 64 * 68 + 2 * 32 * 66 + 32 * 68) * sizeof(float);
    cudaFuncSetAttribute(k_gemm, cudaFuncAttributeMaxDynamicSharedMemorySize,
                         (int)gemm_smem);

    // 20480 rows total (4096 weight rows + 16384 x rows), 32 rows per CTA.
    k_dft<<<640, 256>>>(x, w);
    k_gemm<<<dim3(8, 33), 256, gemm_smem>>>();
    k_inv<<<512, 256>>>((float*)d_out);
}

// round 10
// speedup vs baseline: 1.0128x; 1.0128x over previous
#include <cuda_runtime.h>

// Sizes: x (256,4096) f32, weights (64,64,64) f32, out (256,4096) f32.
// out[b, f*64+n] = sum_c sum_m w[f,c,m] * x[b, c*64 + (n-m) mod 64]
// computed in the 64-point DFT domain with rfft symmetry (33 freqs).

#define NF 33
#define BSZ 256
#define CC 64
#define FF 64

// [k][row] planes. Wf rows = f*64+c (4096), Xf rows = b*64+c (16384),
// S rows = b*64+f (16384).
__device__ float2 g_Wf[NF * FF * CC];
__device__ float2 g_Xf[NF * BSZ * CC];
__device__ float2 g_S [NF * BSZ * FF];

// ---------------------------------------------------------------------------
// Kernel 1: forward rDFT of every length-64 row (4096 w-rows + 16384 x-rows).
// Radix-2 m-split: e[j] = v[j]+v[j+32], o[j] = v[j]-v[j+32];
//   X[k] = sum_{j<32} u[j] tw[(jk)&63],  u = e (k even) / o (k odd)
// plus a j-fold:  X[k] = P[k] + (-i)^k Q[k],
//   P = sum_{j<16} u[j] B[j][k],  Q = sum_{j<16} u[j+16] B[j][k]
// so lane k keeps its 16 basis values IN REGISTERS; the hot loop is
// 2 broadcast LDS.128 + 16 reg-FMA per j, fully unrolled (load batching).
// X[32] = sum_j (-1)^j e[j] via staging-phase partials.
// CTA = 32 rows x 256 thr (warp = 4 rows, lane = k), grid 640.
// ---------------------------------------------------------------------------
__global__ void __launch_bounds__(256, 3) k_dft(const float* __restrict__ x,
                                                const float* __restrict__ w) {
    __shared__ float  esm[32][36];    // [j][r]
    __shared__ float  osm[32][36];
    __shared__ float  psm[8][36];     // [hq][r] parity partials
    __shared__ float2 Bsm[16][33];    // [j][k], j < 16
    __shared__ float2 outsm[33][34];  // [k][r]
    __shared__ float2 tw[64];

    const int t = threadIdx.x;
    const int warp = t >> 5, lane = t & 31;

    if (t < 64) {
        float s, c;
        sincospif(-(float)t * (1.0f / 32.0f), &s, &c);
        tw[t] = make_float2(c, s);
    }
    __syncthreads();
#pragma unroll
    for (int i = t; i < 512; i += 256) {
        const int j = i >> 5, k = i & 31;
        Bsm[j][k] = tw[(j * k) & 63];
    }

    const int row0 = blockIdx.x * 32;
    const bool isW = row0 < FF * CC;          // first 128 CTAs exactly
    const float* src = isW ? (w + row0 * 64) : (x + (row0 - FF * CC) * 64);
    float2* base = isW ? g_Wf : g_Xf;
    const int plane = isW ? (FF * CC) : (BSZ * CC);
    const int roff = isW ? row0 : (row0 - FF * CC);

    // ---- stage: thread = (row r, quarter hq); coalesced 128B-run loads ----
    {
        const int r = t >> 3;        // 0..31
        const int hq = t & 7;
        const float4* s4 = (const float4*)src;
        const float4 a  = s4[r * 16 + hq];
        const float4 bq = s4[r * 16 + hq + 8];
        const float e0 = a.x + bq.x, e1 = a.y + bq.y;
        const float e2 = a.z + bq.z, e3 = a.w + bq.w;
        esm[4 * hq + 0][r] = e0;  osm[4 * hq + 0][r] = a.x - bq.x;
        esm[4 * hq + 1][r] = e1;  osm[4 * hq + 1][r] = a.y - bq.y;
        esm[4 * hq + 2][r] = e2;  osm[4 * hq + 2][r] = a.z - bq.z;
        esm[4 * hq + 3][r] = e3;  osm[4 * hq + 3][r] = a.w - bq.w;
        psm[hq][r] = e0 - e1 + e2 - e3;       // j = 4hq starts even
    }
    __syncthreads();

    // ---- k = 32 plane into outsm ----
    if (t < 32) {
        float p = 0.0f;
#pragma unroll
        for (int hq = 0; hq < 8; hq++) p += psm[hq][t];
        outsm[32][t] = make_float2(p, 0.0f);
    }

    // ---- basis for this lane into registers ----
    float2 B[16];
#pragma unroll
    for (int j = 0; j < 16; j++) B[j] = Bsm[j][lane];

    // ---- compute: warp = 4 rows, lane = frequency k ----
    const int r0 = warp * 4;
    const float* ub = (lane & 1) ? &osm[0][0] : &esm[0][0];

    float Pr[4] = {}, Pi[4] = {}, Qr[4] = {}, Qi[4] = {};
#pragma unroll
    for (int j = 0; j < 16; j++) {
        const float4 vP = *(const float4*)(ub + j * 36 + r0);
        const float4 vQ = *(const float4*)(ub + (j + 16) * 36 + r0);
        const float br = B[j].x, bi = B[j].y;
        Pr[0] = fmaf(vP.x, br, Pr[0]);  Pi[0] = fmaf(vP.x, bi, Pi[0]);
        Pr[1] = fmaf(vP.y, br, Pr[1]);  Pi[1] = fmaf(vP.y, bi, Pi[1]);
        Pr[2] = fmaf(vP.z, br, Pr[2]);  Pi[2] = fmaf(vP.z, bi, Pi[2]);
        Pr[3] = fmaf(vP.w, br, Pr[3]);  Pi[3] = fmaf(vP.w, bi, Pi[3]);
        Qr[0] = fmaf(vQ.x, br, Qr[0]);  Qi[0] = fmaf(vQ.x, bi, Qi[0]);
        Qr[1] = fmaf(vQ.y, br, Qr[1]);  Qi[1] = fmaf(vQ.y, bi, Qi[1]);
        Qr[2] = fmaf(vQ.z, br, Qr[2]);  Qi[2] = fmaf(vQ.z, bi, Qi[2]);
        Qr[3] = fmaf(vQ.w, br, Qr[3]);  Qi[3] = fmaf(vQ.w, bi, Qi[3]);
    }

    // ---- fold combine: X = P + (-i)^k Q ----
    //   k%4==0: (Pr+Qr, Pi+Qi)   k%4==1: (Pr+Qi, Pi-Qr)
    //   k%4==2: (Pr-Qr, Pi-Qi)   k%4==3: (Pr-Qi, Pi+Qr)
    {
        const bool sw = (lane & 1);
        const float s1 = (lane & 2) ? -1.0f : 1.0f;
        const float s2 = ((lane + 1) & 2) ? -1.0f : 1.0f;
        float ar[4], ai[4];
#pragma unroll
        for (int m = 0; m < 4; m++) {
            const float t1 = sw ? Qi[m] : Qr[m];
            const float t2 = sw ? Qr[m] : Qi[m];
            ar[m] = fmaf(s1, t1, Pr[m]);
            ai[m] = fmaf(s2, t2, Pi[m]);
        }
        float4* o4 = (float4*)&outsm[lane][r0];
        o4[0] = make_float4(ar[0], ai[0], ar[1], ai[1]);
        o4[1] = make_float4(ar[2], ai[2], ar[3], ai[3]);
    }
    __syncthreads();

    // ---- coalesced stores: 256B runs within each k plane ----
#pragma unroll
    for (int i = t; i < 33 * 32; i += 256) {
        const int k = i >> 5, rl = i & 31;
        base[k * plane + roff + rl] = outsm[k][rl];
    }
}

// ---------------------------------------------------------------------------
// Kernel 2: per-frequency complex GEMM, plain 4-mult, c-vectorized.
// Grid (8 btiles x 2 ftiles, 33 freqs) = 528 CTAs, 256 thr, smem 34KB ->
// single wave, ~3.6 CTAs/SM. Tile 32b x 32f over 64 c; thread = 2b x 2f.
// ---------------------------------------------------------------------------
__global__ void __launch_bounds__(256) k_gemm() {
    extern __shared__ float2 sm2[];
    float2* Xs = sm2;            // [32][66]
    float2* Ws = sm2 + 32 * 66;  // [32][66]

    const int k  = blockIdx.y;
    const int b0 = (blockIdx.x & 7) * 32;
    const int f0 = (blockIdx.x >> 3) * 32;
    const float2* gX = g_Xf + k * (BSZ * CC) + b0 * CC;
    const float2* gW = g_Wf + k * (FF * CC) + f0 * CC;

#pragma unroll
    for (int i = threadIdx.x; i < 2048; i += 256) {
        const int r = i >> 6, c = i & 63;
        Xs[r * 66 + c] = gX[i];
        Ws[r * 66 + c] = gW[i];
    }
    __syncthreads();

    const int tf = threadIdx.x & 15;   // f = f0 + tf + 16*i (i<2)
    const int tb = threadIdx.x >> 4;   // b = b0 + tb + 16*j (j<2)

    float Sr[2][2] = {}, Si[2][2] = {};
#pragma unroll 4
    for (int c = 0; c < 64; c += 2) {
        float4 xv[2], wv[2];
#pragma unroll
        for (int j = 0; j < 2; j++)
            xv[j] = *(const float4*)&Xs[(tb + 16 * j) * 66 + c];
#pragma unroll
        for (int i = 0; i < 2; i++)
            wv[i] = *(const float4*)&Ws[(tf + 16 * i) * 66 + c];
#pragma unroll
        for (int j = 0; j < 2; j++)
#pragma unroll
            for (int i = 0; i < 2; i++) {
                // c
                Sr[j][i] = fmaf(xv[j].x, wv[i].x, Sr[j][i]);
                Sr[j][i] = fmaf(-xv[j].y, wv[i].y, Sr[j][i]);
                Si[j][i] = fmaf(xv[j].x, wv[i].y, Si[j][i]);
                Si[j][i] = fmaf(xv[j].y, wv[i].x, Si[j][i]);
                // c + 1
                Sr[j][i] = fmaf(xv[j].z, wv[i].z, Sr[j][i]);
                Sr[j][i] = fmaf(-xv[j].w, wv[i].w, Sr[j][i]);
                Si[j][i] = fmaf(xv[j].z, wv[i].w, Si[j][i]);
                Si[j][i] = fmaf(xv[j].w, wv[i].z, Si[j][i]);
            }
    }

    float2* gS = g_S + k * (BSZ * FF) + b0 * FF + f0;
#pragma unroll
    for (int j = 0; j < 2; j++)
#pragma unroll
        for (int i = 0; i < 2; i++)
            gS[(tb + 16 * j) * FF + tf + 16 * i] =
                make_float2(Sr[j][i], Si[j][i]);
}

// ---------------------------------------------------------------------------
// Kernel 3: real inverse transform with n / n+32 symmetry:
//   out[r][n]    = E[r][n] + O[r][n]
//   out[r][n+32] = E[r][n] - O[r][n]      (n < 32)
//   E over even k, O over odd k, Bm[k][n] = (s_k cos, -s_k sin),
//   s_k = 1/64 for k in {0,32} else 2/64.
// CTA = 32 rows x 256 thr -> 512 CTAs (~3.5/SM). Thread = (row, 4-wide n).
// ---------------------------------------------------------------------------
__global__ void __launch_bounds__(256) k_inv(float* __restrict__ out) {
    __shared__ float2 Ssh[32][NF];   // [row][k]
    __shared__ float2 Bm[NF][32];    // n < 32 only
    __shared__ float2 tw[64];

    const int t = threadIdx.x;
    if (t < 64) {
        float s, c;
        sincospif((float)t * (1.0f / 32.0f), &s, &c);
        tw[t] = make_float2(c, s);
    }
    __syncthreads();
#pragma unroll
    for (int i = t; i < NF * 32; i += 256) {
        const int k = i >> 5, n = i & 31;
        const float sc = (k == 0 || k == 32) ? (1.0f / 64.0f) : (2.0f / 64.0f);
        const float2 wv = tw[(k * n) & 63];
        Bm[k][n] = make_float2(sc * wv.x, -sc * wv.y);
    }

    const int r0 = blockIdx.x * 32;
#pragma unroll
    for (int i = t; i < 32 * NF; i += 256) {
        const int rl = i & 31, k = i >> 5;
        Ssh[rl][k] = g_S[k * (BSZ * FF) + r0 + rl];
    }
    __syncthreads();

    const int ng  = t & 7;    // n = ng*4 .. ng*4+3 (lower half)
    const int row = t >> 3;   // 0..31

    float e[4] = {}, o[4] = {};
#pragma unroll
    for (int kk = 0; kk < 17; kk++) {          // even k = 0,2,...,32
        const int k = 2 * kk;
        const float2 sv = Ssh[row][k];
        const float4 b01 = *(const float4*)&Bm[k][ng * 4];
        const float4 b23 = *(const float4*)&Bm[k][ng * 4 + 2];
        e[0] = fmaf(sv.x, b01.x, e[0]);  e[0] = fmaf(sv.y, b01.y, e[0]);
        e[1] = fmaf(sv.x, b01.z, e[1]);  e[1] = fmaf(sv.y, b01.w, e[1]);
        e[2] = fmaf(sv.x, b23.x, e[2]);  e[2] = fmaf(sv.y, b23.y, e[2]);
        e[3] = fmaf(sv.x, b23.z, e[3]);  e[3] = fmaf(sv.y, b23.w, e[3]);
    }
#pragma unroll
    for (int kk = 0; kk < 16; kk++) {          // odd k = 1,3,...,31
        const int k = 2 * kk + 1;
        const float2 sv = Ssh[row][k];
        const float4 b01 = *(const float4*)&Bm[k][ng * 4];
        const float4 b23 = *(const float4*)&Bm[k][ng * 4 + 2];
        o[0] = fmaf(sv.x, b01.x, o[0]);  o[0] = fmaf(sv.y, b01.y, o[0]);
        o[1] = fmaf(sv.x, b01.z, o[1]);  o[1] = fmaf(sv.y, b01.w, o[1]);
        o[2] = fmaf(sv.x, b23.x, o[2]);  o[2] = fmaf(sv.y, b23.y, o[2]);
        o[3] = fmaf(sv.x, b23.z, o[3]);  o[3] = fmaf(sv.y, b23.w, o[3]);
    }

    float* obase = out + (r0 + row) * 64 + ng * 4;
    *(float4*)obase = make_float4(e[0] + o[0], e[1] + o[1],
                                  e[2] + o[2], e[3] + o[3]);
    *(float4*)(obase + 32) = make_float4(e[0] - o[0], e[1] - o[1],
                                         e[2] - o[2], e[3] - o[3]);
}

// ---------------------------------------------------------------------------
extern "C" void kernel_launch(void* const* d_in, const int* in_sizes, int n_in,
                              void* d_out, int out_size) {
    const float* x = (const float*)d_in[0];
    const float* w = (const float*)d_in[1];
    // Defensive: identify by element count (x = 1048576, w = 262144).
    if (n_in >= 2 && in_sizes[0] == 64 * 64 * 64) {
        x = (const float*)d_in[1];
        w = (const float*)d_in[0];
    }

    // 2 x [32][66] float2 = 33792 bytes
    static const size_t gemm_smem = 2 * 32 * 66 * sizeof(float2);
    cudaFuncSetAttribute(k_gemm, cudaFuncAttributeMaxDynamicSharedMemorySize,
                         (int)gemm_smem);

    // 20480 rows total (4096 weight rows + 16384 x rows), 32 rows per CTA.
    k_dft<<<640, 256>>>(x, w);
    k_gemm<<<dim3(16, 33), 256, gemm_smem>>>();
    k_inv<<<512, 256>>>((float*)d_out);
}

// round 11
// speedup vs baseline: 1.0362x; 1.0231x over previous
#include <cuda_runtime.h>

// Sizes: x (256,4096) f32, weights (64,64,64) f32, out (256,4096) f32.
// out[b, f*64+n] = sum_c sum_m w[f,c,m] * x[b, c*64 + (n-m) mod 64]
// computed in the 64-point DFT domain with rfft symmetry (33 freqs).

#define NF 33
#define BSZ 256
#define CC 64
#define FF 64

// [k][row] planes. Wf rows = f*64+c (4096), Xf rows = b*64+c (16384),
// S rows = b*64+f (16384).
__device__ float2 g_Wf[NF * FF * CC];
__device__ float2 g_Xf[NF * BSZ * CC];
__device__ float2 g_S [NF * BSZ * FF];

// ---------------------------------------------------------------------------
// Kernel 1: forward rDFT of every length-64 row (4096 w-rows + 16384 x-rows).
// Radix-2 m-split + j-fold (X = P + (-i)^k Q); lane k keeps its 16 basis
// values in registers; hot loop = 2 broadcast LDS.128 + 16 reg-FMA per j.
// X[32] = parity sum from staging phase. CTA = 32 rows x 256 thr, grid 640,
// 4 CTAs/SM residency cap.
// ---------------------------------------------------------------------------
__global__ void __launch_bounds__(256, 4) k_dft(const float* __restrict__ x,
                                                const float* __restrict__ w) {
    __shared__ float  esm[32][36];    // [j][r]
    __shared__ float  osm[32][36];
    __shared__ float  psm[8][36];     // [hq][r] parity partials
    __shared__ float2 Bsm[16][33];    // [j][k], j < 16
    __shared__ float2 outsm[33][34];  // [k][r]
    __shared__ float2 tw[64];

    const int t = threadIdx.x;
    const int warp = t >> 5, lane = t & 31;

    if (t < 64) {
        float s, c;
        sincospif(-(float)t * (1.0f / 32.0f), &s, &c);
        tw[t] = make_float2(c, s);
    }
    __syncthreads();
#pragma unroll
    for (int i = t; i < 512; i += 256) {
        const int j = i >> 5, k = i & 31;
        Bsm[j][k] = tw[(j * k) & 63];
    }

    const int row0 = blockIdx.x * 32;
    const bool isW = row0 < FF * CC;          // first 128 CTAs exactly
    const float* src = isW ? (w + row0 * 64) : (x + (row0 - FF * CC) * 64);
    float2* base = isW ? g_Wf : g_Xf;
    const int plane = isW ? (FF * CC) : (BSZ * CC);
    const int roff = isW ? row0 : (row0 - FF * CC);

    // ---- stage: thread = (row r, quarter hq); coalesced 128B-run loads ----
    {
        const int r = t >> 3;        // 0..31
        const int hq = t & 7;
        const float4* s4 = (const float4*)src;
        const float4 a  = s4[r * 16 + hq];
        const float4 bq = s4[r * 16 + hq + 8];
        const float e0 = a.x + bq.x, e1 = a.y + bq.y;
        const float e2 = a.z + bq.z, e3 = a.w + bq.w;
        esm[4 * hq + 0][r] = e0;  osm[4 * hq + 0][r] = a.x - bq.x;
        esm[4 * hq + 1][r] = e1;  osm[4 * hq + 1][r] = a.y - bq.y;
        esm[4 * hq + 2][r] = e2;  osm[4 * hq + 2][r] = a.z - bq.z;
        esm[4 * hq + 3][r] = e3;  osm[4 * hq + 3][r] = a.w - bq.w;
        psm[hq][r] = e0 - e1 + e2 - e3;       // j = 4hq starts even
    }
    __syncthreads();

    // ---- k = 32 plane into outsm ----
    if (t < 32) {
        float p = 0.0f;
#pragma unroll
        for (int hq = 0; hq < 8; hq++) p += psm[hq][t];
        outsm[32][t] = make_float2(p, 0.0f);
    }

    // ---- basis for this lane into registers ----
    float2 B[16];
#pragma unroll
    for (int j = 0; j < 16; j++) B[j] = Bsm[j][lane];

    // ---- compute: warp = 4 rows, lane = frequency k ----
    const int r0 = warp * 4;
    const float* ub = (lane & 1) ? &osm[0][0] : &esm[0][0];

    float Pr[4] = {}, Pi[4] = {}, Qr[4] = {}, Qi[4] = {};
#pragma unroll
    for (int j = 0; j < 16; j++) {
        const float4 vP = *(const float4*)(ub + j * 36 + r0);
        const float4 vQ = *(const float4*)(ub + (j + 16) * 36 + r0);
        const float br = B[j].x, bi = B[j].y;
        Pr[0] = fmaf(vP.x, br, Pr[0]);  Pi[0] = fmaf(vP.x, bi, Pi[0]);
        Pr[1] = fmaf(vP.y, br, Pr[1]);  Pi[1] = fmaf(vP.y, bi, Pi[1]);
        Pr[2] = fmaf(vP.z, br, Pr[2]);  Pi[2] = fmaf(vP.z, bi, Pi[2]);
        Pr[3] = fmaf(vP.w, br, Pr[3]);  Pi[3] = fmaf(vP.w, bi, Pi[3]);
        Qr[0] = fmaf(vQ.x, br, Qr[0]);  Qi[0] = fmaf(vQ.x, bi, Qi[0]);
        Qr[1] = fmaf(vQ.y, br, Qr[1]);  Qi[1] = fmaf(vQ.y, bi, Qi[1]);
        Qr[2] = fmaf(vQ.z, br, Qr[2]);  Qi[2] = fmaf(vQ.z, bi, Qi[2]);
        Qr[3] = fmaf(vQ.w, br, Qr[3]);  Qi[3] = fmaf(vQ.w, bi, Qi[3]);
    }

    // ---- fold combine: X = P + (-i)^k Q ----
    {
        const bool sw = (lane & 1);
        const float s1 = (lane & 2) ? -1.0f : 1.0f;
        const float s2 = ((lane + 1) & 2) ? -1.0f : 1.0f;
        float ar[4], ai[4];
#pragma unroll
        for (int m = 0; m < 4; m++) {
            const float t1 = sw ? Qi[m] : Qr[m];
            const float t2 = sw ? Qr[m] : Qi[m];
            ar[m] = fmaf(s1, t1, Pr[m]);
            ai[m] = fmaf(s2, t2, Pi[m]);
        }
        float4* o4 = (float4*)&outsm[lane][r0];
        o4[0] = make_float4(ar[0], ai[0], ar[1], ai[1]);
        o4[1] = make_float4(ar[2], ai[2], ar[3], ai[3]);
    }
    __syncthreads();

    // ---- coalesced stores: 256B runs within each k plane ----
#pragma unroll
    for (int i = t; i < 33 * 32; i += 256) {
        const int k = i >> 5, rl = i & 31;
        base[k * plane + roff + rl] = outsm[k][rl];
    }
}

// ---------------------------------------------------------------------------
// Kernel 2: per-frequency complex GEMM, Karatsuba 3-mult (floor 6.1us vs
// 8.1us for 4-mult at 64 FFMA/SM/cyc). Grid (4 btiles x 2 ftiles, 33) =
// 264 CTAs, 256 thr, smem ~76KB -> 2 CTAs/SM. Tile 64b x 32f over 64 c;
// thread = 4b x 2f. W and Wsum stored TRANSPOSED [c][f] so warp reads are
// contiguous 128B (conflict-free); X reads are 2-address broadcasts.
//   Re = a1 - a2,  Im = a3 - a1 - a2
//   a1 = sum xr*wr, a2 = sum xi*wi, a3 = sum (xr+xi)*(wr+wi)
// ---------------------------------------------------------------------------
__global__ void __launch_bounds__(256) k_gemm() {
    extern __shared__ float smf[];
    float2* Xs    = (float2*)smf;                       // [64][66]
    float*  Xsum  = smf + 2 * 64 * 66;                  // [64][68]
    float2* Wt    = (float2*)(smf + 2 * 64 * 66 + 64 * 68);   // [64c][34f]
    float*  Wsumt = smf + 2 * 64 * 66 + 64 * 68 + 2 * 64 * 34; // [64c][36f]

    const int k  = blockIdx.y;
    const int b0 = (blockIdx.x & 3) * 64;
    const int f0 = (blockIdx.x >> 2) * 32;
    const float2* gX = g_Xf + k * (BSZ * CC) + b0 * CC;
    const float2* gW = g_Wf + k * (FF * CC) + f0 * CC;

#pragma unroll
    for (int i = threadIdx.x; i < 4096; i += 256) {
        const int r = i >> 6, c = i & 63;
        const float2 xv = gX[i];
        Xs[r * 66 + c] = xv;
        Xsum[r * 68 + c] = xv.x + xv.y;
    }
#pragma unroll
    for (int i = threadIdx.x; i < 2048; i += 256) {
        const int r = i >> 6, c = i & 63;   // r = f-row
        const float2 wv = gW[i];
        Wt[c * 34 + r] = wv;
        Wsumt[c * 36 + r] = wv.x + wv.y;
    }
    __syncthreads();

    const int tf = threadIdx.x & 15;   // f = f0 + tf + 16*i (i<2)
    const int tb = threadIdx.x >> 4;   // b = b0 + tb + 16*j (j<4)

    float a1[4][2] = {}, a2[4][2] = {}, a3[4][2] = {};
#pragma unroll 4
    for (int c = 0; c < 64; c += 2) {
        float4 xv[4];
        float2 xs[4];
#pragma unroll
        for (int j = 0; j < 4; j++) {
            const int b = tb + 16 * j;
            xv[j] = *(const float4*)&Xs[b * 66 + c];      // (re,im) x 2 c's
            xs[j] = *(const float2*)&Xsum[b * 68 + c];
        }
        float2 w0[2], w1[2];
        float  ws0[2], ws1[2];
#pragma unroll
        for (int i = 0; i < 2; i++) {
            const int f = tf + 16 * i;
            w0[i]  = Wt[c * 34 + f];
            w1[i]  = Wt[(c + 1) * 34 + f];
            ws0[i] = Wsumt[c * 36 + f];
            ws1[i] = Wsumt[(c + 1) * 36 + f];
        }
#pragma unroll
        for (int j = 0; j < 4; j++)
#pragma unroll
            for (int i = 0; i < 2; i++) {
                a1[j][i] = fmaf(xv[j].x, w0[i].x, a1[j][i]);
                a2[j][i] = fmaf(xv[j].y, w0[i].y, a2[j][i]);
                a3[j][i] = fmaf(xs[j].x, ws0[i],  a3[j][i]);
                a1[j][i] = fmaf(xv[j].z, w1[i].x, a1[j][i]);
                a2[j][i] = fmaf(xv[j].w, w1[i].y, a2[j][i]);
                a3[j][i] = fmaf(xs[j].y, ws1[i],  a3[j][i]);
            }
    }

    float2* gS = g_S + k * (BSZ * FF) + b0 * FF + f0;
#pragma unroll
    for (int j = 0; j < 4; j++)
#pragma unroll
        for (int i = 0; i < 2; i++) {
            const float re = a1[j][i] - a2[j][i];
            const float im = a3[j][i] - a1[j][i] - a2[j][i];
            gS[(tb + 16 * j) * FF + tf + 16 * i] = make_float2(re, im);
        }
}

// ---------------------------------------------------------------------------
// Kernel 3: real inverse transform with n / n+32 symmetry:
//   out[r][n]    = E[r][n] + O[r][n]
//   out[r][n+32] = E[r][n] - O[r][n]      (n < 32)
//   E over even k, O over odd k, Bm[k][n] = (s_k cos, -s_k sin),
//   s_k = 1/64 for k in {0,32} else 2/64.
// CTA = 32 rows x 256 thr -> 512 CTAs (~3.5/SM). Thread = (row, 4-wide n).
// ---------------------------------------------------------------------------
__global__ void __launch_bounds__(256) k_inv(float* __restrict__ out) {
    __shared__ float2 Ssh[32][NF];   // [row][k]
    __shared__ float2 Bm[NF][32];    // n < 32 only
    __shared__ float2 tw[64];

    const int t = threadIdx.x;
    if (t < 64) {
        float s, c;
        sincospif((float)t * (1.0f / 32.0f), &s, &c);
        tw[t] = make_float2(c, s);
    }
    __syncthreads();
#pragma unroll
    for (int i = t; i < NF * 32; i += 256) {
        const int k = i >> 5, n = i & 31;
        const float sc = (k == 0 || k == 32) ? (1.0f / 64.0f) : (2.0f / 64.0f);
        const float2 wv = tw[(k * n) & 63];
        Bm[k][n] = make_float2(sc * wv.x, -sc * wv.y);
    }

    const int r0 = blockIdx.x * 32;
#pragma unroll
    for (int i = t; i < 32 * NF; i += 256) {
        const int rl = i & 31, k = i >> 5;
        Ssh[rl][k] = g_S[k * (BSZ * FF) + r0 + rl];
    }
    __syncthreads();

    const int ng  = t & 7;    // n = ng*4 .. ng*4+3 (lower half)
    const int row = t >> 3;   // 0..31

    float e[4] = {}, o[4] = {};
#pragma unroll
    for (int kk = 0; kk < 17; kk++) {          // even k = 0,2,...,32
        const int k = 2 * kk;
        const float2 sv = Ssh[row][k];
        const float4 b01 = *(const float4*)&Bm[k][ng * 4];
        const float4 b23 = *(const float4*)&Bm[k][ng * 4 + 2];
        e[0] = fmaf(sv.x, b01.x, e[0]);  e[0] = fmaf(sv.y, b01.y, e[0]);
        e[1] = fmaf(sv.x, b01.z, e[1]);  e[1] = fmaf(sv.y, b01.w, e[1]);
        e[2] = fmaf(sv.x, b23.x, e[2]);  e[2] = fmaf(sv.y, b23.y, e[2]);
        e[3] = fmaf(sv.x, b23.z, e[3]);  e[3] = fmaf(sv.y, b23.w, e[3]);
    }
#pragma unroll
    for (int kk = 0; kk < 16; kk++) {          // odd k = 1,3,...,31
        const int k = 2 * kk + 1;
        const float2 sv = Ssh[row][k];
        const float4 b01 = *(const float4*)&Bm[k][ng * 4];
        const float4 b23 = *(const float4*)&Bm[k][ng * 4 + 2];
        o[0] = fmaf(sv.x, b01.x, o[0]);  o[0] = fmaf(sv.y, b01.y, o[0]);
        o[1] = fmaf(sv.x, b01.z, o[1]);  o[1] = fmaf(sv.y, b01.w, o[1]);
        o[2] = fmaf(sv.x, b23.x, o[2]);  o[2] = fmaf(sv.y, b23.y, o[2]);
        o[3] = fmaf(sv.x, b23.z, o[3]);  o[3] = fmaf(sv.y, b23.w, o[3]);
    }

    float* obase = out + (r0 + row) * 64 + ng * 4;
    *(float4*)obase = make_float4(e[0] + o[0], e[1] + o[1],
                                  e[2] + o[2], e[3] + o[3]);
    *(float4*)(obase + 32) = make_float4(e[0] - o[0], e[1] - o[1],
                                         e[2] - o[2], e[3] - o[3]);
}

// ---------------------------------------------------------------------------
extern "C" void kernel_launch(void* const* d_in, const int* in_sizes, int n_in,
                              void* d_out, int out_size) {
    const float* x = (const float*)d_in[0];
    const float* w = (const float*)d_in[1];
    // Defensive: identify by element count (x = 1048576, w = 262144).
    if (n_in >= 2 && in_sizes[0] == 64 * 64 * 64) {
        x = (const float*)d_in[1];
        w = (const float*)d_in[0];
    }

    // Xs 33792 + Xsum 17408 + Wt 17408 + Wsumt 9216 = 77824 bytes
    static const size_t gemm_smem =
        (2 * 64 * 66 + 64 * 68 + 2 * 64 * 34 + 64 * 36) * sizeof(float);
    cudaFuncSetAttribute(k_gemm, cudaFuncAttributeMaxDynamicSharedMemorySize,
                         (int)gemm_smem);

    // 20480 rows total (4096 weight rows + 16384 x rows), 32 rows per CTA.
    k_dft<<<640, 256>>>(x, w);
    k_gemm<<<dim3(8, 33), 256, gemm_smem>>>();
    k_inv<<<512, 256>>>((float*)d_out);
}